// round 5
// baseline (speedup 1.0000x reference)
#include <cuda_runtime.h>

#define DD 512
#define BB 128
#define EPSF 1e-5f
#define LOG2E_F 1.4426950408889634f
#define TJ 32
#define MATSZ (384 * 512)        // 196608

// scratch (static device memory — no allocations)
__device__ float g_wk[3 * BB * DD];
__device__ float g_wq[3 * BB * DD];
__device__ float g_y [3 * BB * DD];
__device__ float g_wt[3 * DD * DD];     // k-major weights: [mat][k][m]
__device__ float g_st[2 * MATSZ];       // k-major sources: [mat][k][row]  (H, KQ)
__device__ float g_yT[MATSZ];           // k-major y: [k][row]
__device__ float g_part[4 * MATSZ];     // K-split partials

struct Ptr3 { const float* p[3]; };

__device__ __forceinline__ float ex2f(float x) {
    float y;
    asm("ex2.approx.ftz.f32 %0, %1;" : "=f"(y) : "f"(x));
    return y;
}

// ===================== transpose weights: g_wt[z][d][m] = W_z[m][d] =====================
__global__ void __launch_bounds__(256)
k_transpose(const float* __restrict__ W0, const float* __restrict__ W1,
            const float* __restrict__ W2)
{
    __shared__ float t[32][33];
    const float* W = (blockIdx.z == 0) ? W0 : (blockIdx.z == 1) ? W1 : W2;
    float* O = g_wt + (size_t)blockIdx.z * DD * DD;
    int x  = blockIdx.x * 32 + threadIdx.x;
    int y0 = blockIdx.y * 32;
    #pragma unroll
    for (int i = threadIdx.y; i < 32; i += 8)
        t[i][threadIdx.x] = W[(size_t)(y0 + i) * DD + x];
    __syncthreads();
    int xo  = blockIdx.y * 32 + threadIdx.x;
    int yo0 = blockIdx.x * 32;
    #pragma unroll
    for (int i = threadIdx.y; i < 32; i += 8)
        O[(size_t)(yo0 + i) * DD + xo] = t[threadIdx.x][i];
}

// ===================== transpose sources: g_st[z][k][row] = src_z[row][k] =====================
// rows = 384 (3 channels x 128), cols = 512. grid (16, 12, 2), block (32, 8)
__global__ void __launch_bounds__(256)
k_transpose2(Ptr3 A, Ptr3 B)
{
    __shared__ float tl[32][33];
    int z = blockIdx.z;
    Ptr3 S = z ? B : A;
    float* dst = g_st + (size_t)z * MATSZ;
    int col0 = blockIdx.x * 32;     // feature (k) dim
    int row0 = blockIdx.y * 32;     // row dim
    int tx = threadIdx.x;
    #pragma unroll
    for (int i = threadIdx.y; i < 32; i += 8) {
        int row = row0 + i;
        const float* p = S.p[row >> 7];
        tl[i][tx] = p[(size_t)(row & 127) * DD + col0 + tx];
    }
    __syncthreads();
    #pragma unroll
    for (int i = threadIdx.y; i < 32; i += 8)
        dst[(size_t)(col0 + i) * 384 + row0 + tx] = tl[tx][i];
}

// ===================== GEMM v5: smem-staged both operands =====================
// part[z][row][col] = sum_{k in split} srcT[k][row] * wtT[k][col]
// block: 128 thr; tile 32 rows x 64 cols; K staged in chunks of 128.
// grid: (12 row-tiles, 8 col-tiles, nks * nmat)
struct G5 {
    const float* src[2];    // k-major [512][384]
    const float* wt[2];     // k-major [512][512]
    int nks;                // K-splits per matrix
    int chunks;             // K-chunks of 128 per block
};

#define SSTR 36
#define WSTR 68
#define G5_SMEM ((128 * SSTR + 128 * WSTR) * 4)   // 53248 B

__global__ void __launch_bounds__(128)
k_gemm5(G5 a)
{
    extern __shared__ float dsm[];
    float (*s_src)[SSTR] = (float (*)[SSTR])dsm;
    float (*s_wt)[WSTR]  = (float (*)[WSTR])(dsm + 128 * SSTR);

    int t  = threadIdx.x;
    int rt = blockIdx.x, ct = blockIdx.y, z = blockIdx.z;
    int mat = z / a.nks, ks = z % a.nks;
    const float* srcT = a.src[mat];
    const float* wtT  = a.wt[mat];
    int row0 = rt * 32, col0 = ct * 64;
    int k0 = ks * a.chunks * 128;

    int cq = t & 15;      // 16 col-quads
    int rq = t >> 4;      // 8 row-quads

    float acc[4][4];
    #pragma unroll
    for (int i = 0; i < 4; i++)
        #pragma unroll
        for (int j = 0; j < 4; j++) acc[i][j] = 0.0f;

    for (int ch = 0; ch < a.chunks; ch++) {
        int kb = k0 + ch * 128;
        // stage src: 128 k x 32 rows (straight copy, coalesced)
        #pragma unroll
        for (int i = 0; i < 8; i++) {
            int idx = i * 128 + t;
            int k = idx >> 3, r4 = idx & 7;
            ((float4*)&s_src[k][0])[r4] =
                *(const float4*)(srcT + (size_t)(kb + k) * 384 + row0 + 4 * r4);
        }
        // stage wt: 128 k x 64 cols
        #pragma unroll
        for (int i = 0; i < 16; i++) {
            int idx = i * 128 + t;
            int k = idx >> 4, c4 = idx & 15;
            ((float4*)&s_wt[k][0])[c4] =
                *(const float4*)(wtT + (size_t)(kb + k) * DD + col0 + 4 * c4);
        }
        __syncthreads();

        #pragma unroll 4
        for (int k = 0; k < 128; k++) {
            float4 w = ((const float4*)&s_wt[k][0])[cq];
            float4 s = ((const float4*)&s_src[k][0])[rq];
            acc[0][0] = fmaf(s.x, w.x, acc[0][0]);
            acc[0][1] = fmaf(s.x, w.y, acc[0][1]);
            acc[0][2] = fmaf(s.x, w.z, acc[0][2]);
            acc[0][3] = fmaf(s.x, w.w, acc[0][3]);
            acc[1][0] = fmaf(s.y, w.x, acc[1][0]);
            acc[1][1] = fmaf(s.y, w.y, acc[1][1]);
            acc[1][2] = fmaf(s.y, w.z, acc[1][2]);
            acc[1][3] = fmaf(s.y, w.w, acc[1][3]);
            acc[2][0] = fmaf(s.z, w.x, acc[2][0]);
            acc[2][1] = fmaf(s.z, w.y, acc[2][1]);
            acc[2][2] = fmaf(s.z, w.z, acc[2][2]);
            acc[2][3] = fmaf(s.z, w.w, acc[2][3]);
            acc[3][0] = fmaf(s.w, w.x, acc[3][0]);
            acc[3][1] = fmaf(s.w, w.y, acc[3][1]);
            acc[3][2] = fmaf(s.w, w.z, acc[3][2]);
            acc[3][3] = fmaf(s.w, w.w, acc[3][3]);
        }
        __syncthreads();
    }

    float* p = g_part + (size_t)z * MATSZ;
    #pragma unroll
    for (int jr = 0; jr < 4; jr++) {
        float4 v = make_float4(acc[jr][0], acc[jr][1], acc[jr][2], acc[jr][3]);
        *(float4*)(p + (size_t)(row0 + 4 * rq + jr) * DD + col0 + 4 * cq) = v;
    }
}

// ===================== reduce kernels =====================
__global__ void __launch_bounds__(512)
k_reduce1(const float* __restrict__ bk, const float* __restrict__ bq)
{
    int t = threadIdx.x;
    size_t i = (size_t)blockIdx.x * DD + t;
    g_wk[i] = g_part[i] + g_part[MATSZ + i] + bk[t];
    g_wq[i] = g_part[2 * MATSZ + i] + g_part[3 * MATSZ + i] + bq[t];
}

__global__ void __launch_bounds__(512)
k_reduce2(const float* __restrict__ fcb, float* __restrict__ out)
{
    int t = threadIdx.x;
    size_t i = (size_t)blockIdx.x * DD + t;
    out[i] = g_part[i] + g_part[MATSZ + i] + g_part[2 * MATSZ + i]
           + g_part[3 * MATSZ + i] + fcb[t] + g_y[i];
}

// ---- block reductions over 512 threads (16 warps) ----
__device__ __forceinline__ float blockReduceSum(float v, float* red) {
    int tid = threadIdx.x, lane = tid & 31, wid = tid >> 5;
    #pragma unroll
    for (int o = 16; o > 0; o >>= 1) v += __shfl_down_sync(0xffffffffu, v, o);
    if (lane == 0) red[wid] = v;
    __syncthreads();
    if (wid == 0) {
        float x = (lane < 16) ? red[lane] : 0.0f;
        #pragma unroll
        for (int o = 8; o > 0; o >>= 1) x += __shfl_down_sync(0xffffffffu, x, o);
        if (lane == 0) red[0] = x;
    }
    __syncthreads();
    float r = red[0];
    __syncthreads();
    return r;
}

__device__ __forceinline__ float blockReduceMax(float v, float* red) {
    int tid = threadIdx.x, lane = tid & 31, wid = tid >> 5;
    #pragma unroll
    for (int o = 16; o > 0; o >>= 1) v = fmaxf(v, __shfl_down_sync(0xffffffffu, v, o));
    if (lane == 0) red[wid] = v;
    __syncthreads();
    if (wid == 0) {
        float x = (lane < 16) ? red[lane] : -3.4e38f;
        #pragma unroll
        for (int o = 8; o > 0; o >>= 1) x = fmaxf(x, __shfl_down_sync(0xffffffffu, x, o));
        if (lane == 0) red[0] = x;
    }
    __syncthreads();
    float r = red[0];
    __syncthreads();
    return r;
}

__device__ __forceinline__ float blockReduceMin(float v, float* red) {
    int tid = threadIdx.x, lane = tid & 31, wid = tid >> 5;
    #pragma unroll
    for (int o = 16; o > 0; o >>= 1) v = fminf(v, __shfl_down_sync(0xffffffffu, v, o));
    if (lane == 0) red[wid] = v;
    __syncthreads();
    if (wid == 0) {
        float x = (lane < 16) ? red[lane] : 3.4e38f;
        #pragma unroll
        for (int o = 8; o > 0; o >>= 1) x = fminf(x, __shfl_down_sync(0xffffffffu, x, o));
        if (lane == 0) red[0] = x;
    }
    __syncthreads();
    float r = red[0];
    __syncthreads();
    return r;
}

// ---- main fused kernel: one block per (batch, channel) ----
__global__ void __launch_bounds__(512)
k_main(Ptr3 x, Ptr3 h, Ptr3 kq,
       const float* __restrict__ kn_g, const float* __restrict__ kn_b,
       const float* __restrict__ norm_g, const float* __restrict__ norm_b)
{
    extern __shared__ float E[];              // [512][TJ+1]
    __shared__ float s_s[DD], s_u2[DD], s_v[DD];
    __shared__ float Zpart[16][TJ + 1];
    __shared__ float coefT[TJ];
    __shared__ float red[32];

    const int ESTR = TJ + 1;

    int b = blockIdx.x, c = blockIdx.y, tid = threadIdx.x;
    int row = c * BB + b;

    float wk = g_wk[(size_t)row * DD + tid];
    float wq = g_wq[(size_t)row * DD + tid];
    float kv = h.p[c][(size_t)b * DD + tid];
    float qv = kq.p[c][(size_t)b * DD + tid];
    float vv = x.p[c][(size_t)b * DD + tid];

    const float inv_d = 1.0f / (float)DD;
    float mu_wk  = blockReduceSum(wk, red) * inv_d;
    float dk     = wk - mu_wk;
    float var_wk = blockReduceSum(dk * dk, red) * inv_d;
    float mu_wq  = blockReduceSum(wq, red) * inv_d;
    float dq     = wq - mu_wq;
    float var_wq = blockReduceSum(dq * dq, red) * inv_d;

    float gg = kn_g[tid];
    float cb = kn_b[tid];

    float si = kv * rsqrtf(kv * kv * var_wk + EPSF);
    float ti = qv * rsqrtf(qv * qv * var_wq + EPSF);
    float Ai = dk * gg;
    float Bi = dq * gg;

    float P    = blockReduceSum(Ai * ti, red);
    float Qs   = blockReduceSum(Ai, red);
    float smax = blockReduceMax(si, red);
    float smin = blockReduceMin(si, red);

    float u2 = (P * Bi + Qs * cb) * LOG2E_F;
    s_s[tid]  = si;
    s_u2[tid] = u2;
    s_v[tid]  = vv;
    __syncthreads();

    int g = tid >> 5;
    int j = tid & 31;

    float acc = 0.0f;

    #pragma unroll 1
    for (int jt = 0; jt < DD; jt += TJ) {
        float u2j = s_u2[jt + j];
        float m2j = fmaxf(u2j * smax, u2j * smin);
        float Zl = 0.0f;

        float* Ecol = E + (size_t)(g * 32) * ESTR + j;
        const float* sbase = s_s + g * 32;
        #pragma unroll
        for (int i4 = 0; i4 < 32; i4 += 4) {
            float4 s4 = *(const float4*)(sbase + i4);
            float e0 = ex2f(fmaf(s4.x, u2j, -m2j));
            float e1 = ex2f(fmaf(s4.y, u2j, -m2j));
            float e2 = ex2f(fmaf(s4.z, u2j, -m2j));
            float e3 = ex2f(fmaf(s4.w, u2j, -m2j));
            Zl += (e0 + e1) + (e2 + e3);
            Ecol[(i4 + 0) * ESTR] = e0;
            Ecol[(i4 + 1) * ESTR] = e1;
            Ecol[(i4 + 2) * ESTR] = e2;
            Ecol[(i4 + 3) * ESTR] = e3;
        }
        Zpart[g][j] = Zl;
        __syncthreads();

        if (tid < TJ) {
            float zt = 0.0f;
            #pragma unroll
            for (int w = 0; w < 16; w++) zt += Zpart[w][tid];
            coefT[tid] = s_v[jt + tid] / zt;
        }
        __syncthreads();

        const float* Erow = E + (size_t)tid * ESTR;
        #pragma unroll
        for (int jj = 0; jj < TJ; jj += 4) {
            float c0 = coefT[jj + 0], c1 = coefT[jj + 1];
            float c2 = coefT[jj + 2], c3 = coefT[jj + 3];
            acc = fmaf(c0, Erow[jj + 0], acc);
            acc = fmaf(c1, Erow[jj + 1], acc);
            acc = fmaf(c2, Erow[jj + 2], acc);
            acc = fmaf(c3, Erow[jj + 3], acc);
        }
        __syncthreads();
    }

    float y     = acc + vv;
    float mu_y  = blockReduceSum(y, red) * inv_d;
    float dy    = y - mu_y;
    float var_y = blockReduceSum(dy * dy, red) * inv_d;
    float yn    = dy * rsqrtf(var_y + EPSF) * norm_g[tid] + norm_b[tid];

    g_y [(size_t)row * DD + tid] = yn;
    g_yT[(size_t)tid * 384 + row] = yn;   // k-major copy for fc staging
}

extern "C" void kernel_launch(void* const* d_in, const int* in_sizes, int n_in,
                              void* d_out, int out_size)
{
    (void)in_sizes; (void)n_in; (void)out_size;
    const float* r    = (const float*)d_in[0];
    const float* g    = (const float*)d_in[1];
    const float* b    = (const float*)d_in[2];
    const float* h_r  = (const float*)d_in[3];
    const float* h_g  = (const float*)d_in[4];
    const float* h_b  = (const float*)d_in[5];
    const float* k_r  = (const float*)d_in[6];
    const float* k_g  = (const float*)d_in[7];
    const float* k_b  = (const float*)d_in[8];
    const float* Wk   = (const float*)d_in[9];
    const float* bk   = (const float*)d_in[10];
    const float* Wq   = (const float*)d_in[11];
    const float* bq   = (const float*)d_in[12];
    const float* kn_g = (const float*)d_in[13];
    const float* kn_b = (const float*)d_in[14];
    const float* norm_g = (const float*)d_in[15];
    const float* norm_b = (const float*)d_in[16];
    const float* fc_w = (const float*)d_in[17];
    const float* fc_b = (const float*)d_in[18];
    float* out = (float*)d_out;

    Ptr3 X  = {{ r,   g,   b   }};
    Ptr3 H  = {{ h_r, h_g, h_b }};
    Ptr3 KQ = {{ k_r, k_g, k_b }};

    const size_t E_BYTES = (size_t)DD * (TJ + 1) * sizeof(float);

    static float* wt_dev = nullptr;
    static float* st_dev = nullptr;
    static float* yT_dev = nullptr;
    if (wt_dev == nullptr) {
        void* p = nullptr;
        cudaGetSymbolAddress(&p, g_wt); wt_dev = (float*)p;
        cudaGetSymbolAddress(&p, g_st); st_dev = (float*)p;
        cudaGetSymbolAddress(&p, g_yT); yT_dev = (float*)p;
        cudaFuncSetAttribute(k_main, cudaFuncAttributeMaxDynamicSharedMemorySize,
                             (int)E_BYTES);
        cudaFuncSetAttribute(k_gemm5, cudaFuncAttributeMaxDynamicSharedMemorySize,
                             G5_SMEM);
    }

    // Stage 0a: transpose weights -> g_wt
    k_transpose<<<dim3(16, 16, 3), dim3(32, 8)>>>(Wk, Wq, fc_w);
    // Stage 0b: transpose sources -> g_st
    k_transpose2<<<dim3(16, 12, 2), dim3(32, 8)>>>(H, KQ);

    // Stage 1: w_k, w_q partials (nks=2 per matrix, K=256 per block)
    {
        G5 a;
        a.src[0] = st_dev;           a.src[1] = st_dev + MATSZ;
        a.wt[0]  = wt_dev;           a.wt[1]  = wt_dev + DD * DD;
        a.nks = 2; a.chunks = 2;
        k_gemm5<<<dim3(12, 8, 4), 128, G5_SMEM>>>(a);
    }
    k_reduce1<<<384, 512>>>(bk, bq);

    // Stage 2: collapsed attention + residual + LN -> g_y, g_yT
    k_main<<<dim3(BB, 3), 512, E_BYTES>>>(X, H, KQ, kn_g, kn_b, norm_g, norm_b);

    // Stage 3: fc partials (nks=4, K=128 per block)
    {
        G5 a;
        a.src[0] = yT_dev;           a.src[1] = yT_dev;
        a.wt[0]  = wt_dev + 2 * DD * DD;  a.wt[1] = a.wt[0];
        a.nks = 4; a.chunks = 1;
        k_gemm5<<<dim3(12, 8, 4), 128, G5_SMEM>>>(a);
    }
    k_reduce2<<<384, 512>>>(fc_b, out);
}

// round 6
// speedup vs baseline: 1.0450x; 1.0450x over previous
#include <cuda_runtime.h>

#define DD 512
#define BB 128
#define EPSF 1e-5f
#define LOG2E_F 1.4426950408889634f
#define TJ 32

// scratch (static device memory — no allocations)
__device__ float g_wk[3 * BB * DD];
__device__ float g_wq[3 * BB * DD];
__device__ float g_y [3 * BB * DD];
__device__ float g_wt[3 * DD * DD];     // k-major weights: [mat][k][m]

struct Ptr3 { const float* p[3]; };

__device__ __forceinline__ float ex2f(float x) {
    float y;
    asm("ex2.approx.ftz.f32 %0, %1;" : "=f"(y) : "f"(x));
    return y;
}

// ===================== transpose weights: g_wt[z][d][m] = W_z[m][d] =====================
__global__ void __launch_bounds__(256)
k_transpose(const float* __restrict__ W0, const float* __restrict__ W1,
            const float* __restrict__ W2)
{
    __shared__ float t[32][33];
    const float* W = (blockIdx.z == 0) ? W0 : (blockIdx.z == 1) ? W1 : W2;
    float* O = g_wt + (size_t)blockIdx.z * DD * DD;
    int x  = blockIdx.x * 32 + threadIdx.x;
    int y0 = blockIdx.y * 32;
    #pragma unroll
    for (int i = threadIdx.y; i < 32; i += 8)
        t[i][threadIdx.x] = W[(size_t)(y0 + i) * DD + x];
    __syncthreads();
    int xo  = blockIdx.y * 32 + threadIdx.x;
    int yo0 = blockIdx.x * 32;
    #pragma unroll
    for (int i = threadIdx.y; i < 32; i += 8)
        O[(size_t)(yo0 + i) * DD + xo] = t[threadIdx.x][i];
}

// ===================== GEMM v6: smem-staged, full-K, double-buffered weights ==========
// out[row, m] = sum_d src[row, d] * Wt[d, m] + bias[m] (+ residual src[row, m])
// block = 128 thr; tile = 16 rows x 64 cols; K = 512 in 8 chunks of 64.
struct G6 {
    Ptr3 src[2];
    const float* wt[2];      // k-major [512][512]
    const float* bias[2];
    float* out[2];
};

#define G6_SMEM ((16 * DD + 2 * 64 * 64) * 4)    // 32KB src + 32KB wt = 64KB

template <bool RES>
__global__ void __launch_bounds__(128)
k_gemm6(G6 a)
{
    extern __shared__ float dsm[];
    float (*s_src)[DD] = (float (*)[DD])dsm;                // [16][512]
    float (*s_wt)[64][64] = (float (*)[64][64])(dsm + 16 * DD);  // [2][64][64]

    int tid = threadIdx.x;
    int rt = blockIdx.x, ct = blockIdx.y, z = blockIdx.z;
    int r0 = rt * 16;
    const float* src = a.src[z].p[r0 >> 7] + (size_t)(r0 & 127) * DD;
    const float* wt  = a.wt[z] + ct * 64;

    // stage src rows (coalesced float4)
    #pragma unroll
    for (int i = 0; i < 16; i++) {
        int idx = i * 128 + tid;
        int row = idx >> 7, q = idx & 127;
        *(float4*)&s_src[row][q * 4] = *(const float4*)(src + (size_t)row * DD + q * 4);
    }

    int cq = tid & 15;      // 16 col quads -> 64 cols
    int rg = tid >> 4;      // 8 row pairs -> 16 rows

    // prefetch weight chunk 0 into registers
    float4 pf[8];
    #pragma unroll
    for (int i = 0; i < 8; i++) {
        int idx = i * 128 + tid;
        int k = idx >> 4, q = idx & 15;
        pf[i] = *(const float4*)(wt + (size_t)k * DD + q * 4);
    }

    float acc[2][4];
    #pragma unroll
    for (int r = 0; r < 2; r++)
        #pragma unroll
        for (int j = 0; j < 4; j++) acc[r][j] = 0.0f;

    #pragma unroll 1
    for (int ch = 0; ch < 8; ch++) {
        int b = ch & 1;
        #pragma unroll
        for (int i = 0; i < 8; i++) {
            int idx = i * 128 + tid;
            int k = idx >> 4, q = idx & 15;
            *(float4*)&s_wt[b][k][q * 4] = pf[i];
        }
        __syncthreads();
        if (ch < 7) {
            const float* wn = wt + (size_t)(ch + 1) * 64 * DD;
            #pragma unroll
            for (int i = 0; i < 8; i++) {
                int idx = i * 128 + tid;
                int k = idx >> 4, q = idx & 15;
                pf[i] = *(const float4*)(wn + (size_t)k * DD + q * 4);
            }
        }
        int kb = ch * 64;
        #pragma unroll 8
        for (int k2 = 0; k2 < 64; k2 += 2) {
            float4 w0 = *(const float4*)&s_wt[b][k2 + 0][cq * 4];
            float4 w1 = *(const float4*)&s_wt[b][k2 + 1][cq * 4];
            float2 a0 = *(const float2*)&s_src[2 * rg + 0][kb + k2];
            float2 a1 = *(const float2*)&s_src[2 * rg + 1][kb + k2];
            acc[0][0] = fmaf(a0.x, w0.x, fmaf(a0.y, w1.x, acc[0][0]));
            acc[0][1] = fmaf(a0.x, w0.y, fmaf(a0.y, w1.y, acc[0][1]));
            acc[0][2] = fmaf(a0.x, w0.z, fmaf(a0.y, w1.z, acc[0][2]));
            acc[0][3] = fmaf(a0.x, w0.w, fmaf(a0.y, w1.w, acc[0][3]));
            acc[1][0] = fmaf(a1.x, w0.x, fmaf(a1.y, w1.x, acc[1][0]));
            acc[1][1] = fmaf(a1.x, w0.y, fmaf(a1.y, w1.y, acc[1][1]));
            acc[1][2] = fmaf(a1.x, w0.z, fmaf(a1.y, w1.z, acc[1][2]));
            acc[1][3] = fmaf(a1.x, w0.w, fmaf(a1.y, w1.w, acc[1][3]));
        }
        // no trailing sync: next chunk writes the other buffer; the sync above
        // guarantees all warps have finished the chunk before last.
        __syncthreads();
    }

    int col = ct * 64 + cq * 4;
    float4 bb = *(const float4*)(a.bias[z] + col);
    #pragma unroll
    for (int r = 0; r < 2; r++) {
        int row = 2 * rg + r;
        float4 v = make_float4(acc[r][0] + bb.x, acc[r][1] + bb.y,
                               acc[r][2] + bb.z, acc[r][3] + bb.w);
        if (RES) {
            v.x += s_src[row][col + 0];
            v.y += s_src[row][col + 1];
            v.z += s_src[row][col + 2];
            v.w += s_src[row][col + 3];
        }
        *(float4*)(a.out[z] + (size_t)(r0 + row) * DD + col) = v;
    }
}

// ---- block reductions over 512 threads (16 warps) ----
__device__ __forceinline__ float blockReduceSum(float v, float* red) {
    int tid = threadIdx.x, lane = tid & 31, wid = tid >> 5;
    #pragma unroll
    for (int o = 16; o > 0; o >>= 1) v += __shfl_down_sync(0xffffffffu, v, o);
    if (lane == 0) red[wid] = v;
    __syncthreads();
    if (wid == 0) {
        float x = (lane < 16) ? red[lane] : 0.0f;
        #pragma unroll
        for (int o = 8; o > 0; o >>= 1) x += __shfl_down_sync(0xffffffffu, x, o);
        if (lane == 0) red[0] = x;
    }
    __syncthreads();
    float r = red[0];
    __syncthreads();
    return r;
}

__device__ __forceinline__ float blockReduceMax(float v, float* red) {
    int tid = threadIdx.x, lane = tid & 31, wid = tid >> 5;
    #pragma unroll
    for (int o = 16; o > 0; o >>= 1) v = fmaxf(v, __shfl_down_sync(0xffffffffu, v, o));
    if (lane == 0) red[wid] = v;
    __syncthreads();
    if (wid == 0) {
        float x = (lane < 16) ? red[lane] : -3.4e38f;
        #pragma unroll
        for (int o = 8; o > 0; o >>= 1) x = fmaxf(x, __shfl_down_sync(0xffffffffu, x, o));
        if (lane == 0) red[0] = x;
    }
    __syncthreads();
    float r = red[0];
    __syncthreads();
    return r;
}

__device__ __forceinline__ float blockReduceMin(float v, float* red) {
    int tid = threadIdx.x, lane = tid & 31, wid = tid >> 5;
    #pragma unroll
    for (int o = 16; o > 0; o >>= 1) v = fminf(v, __shfl_down_sync(0xffffffffu, v, o));
    if (lane == 0) red[wid] = v;
    __syncthreads();
    if (wid == 0) {
        float x = (lane < 16) ? red[lane] : 3.4e38f;
        #pragma unroll
        for (int o = 8; o > 0; o >>= 1) x = fminf(x, __shfl_down_sync(0xffffffffu, x, o));
        if (lane == 0) red[0] = x;
    }
    __syncthreads();
    float r = red[0];
    __syncthreads();
    return r;
}

// ---- main fused kernel: one block per (batch, channel) ----
__global__ void __launch_bounds__(512)
k_main(Ptr3 x, Ptr3 h, Ptr3 kq,
       const float* __restrict__ kn_g, const float* __restrict__ kn_b,
       const float* __restrict__ norm_g, const float* __restrict__ norm_b)
{
    extern __shared__ float E[];              // [512][TJ+1]
    __shared__ float s_s[DD], s_u2[DD], s_v[DD];
    __shared__ float Zpart[16][TJ + 1];
    __shared__ float coefT[TJ];
    __shared__ float red[32];

    const int ESTR = TJ + 1;

    int b = blockIdx.x, c = blockIdx.y, tid = threadIdx.x;
    int row = c * BB + b;

    float wk = g_wk[(size_t)row * DD + tid];
    float wq = g_wq[(size_t)row * DD + tid];
    float kv = h.p[c][(size_t)b * DD + tid];
    float qv = kq.p[c][(size_t)b * DD + tid];
    float vv = x.p[c][(size_t)b * DD + tid];

    const float inv_d = 1.0f / (float)DD;
    float mu_wk  = blockReduceSum(wk, red) * inv_d;
    float dk     = wk - mu_wk;
    float var_wk = blockReduceSum(dk * dk, red) * inv_d;
    float mu_wq  = blockReduceSum(wq, red) * inv_d;
    float dq     = wq - mu_wq;
    float var_wq = blockReduceSum(dq * dq, red) * inv_d;

    float gg = kn_g[tid];
    float cb = kn_b[tid];

    float si = kv * rsqrtf(kv * kv * var_wk + EPSF);
    float ti = qv * rsqrtf(qv * qv * var_wq + EPSF);
    float Ai = dk * gg;
    float Bi = dq * gg;

    float P    = blockReduceSum(Ai * ti, red);
    float Qs   = blockReduceSum(Ai, red);
    float smax = blockReduceMax(si, red);
    float smin = blockReduceMin(si, red);

    float u2 = (P * Bi + Qs * cb) * LOG2E_F;
    s_s[tid]  = si;
    s_u2[tid] = u2;
    s_v[tid]  = vv;
    __syncthreads();

    int g = tid >> 5;
    int j = tid & 31;

    float acc = 0.0f;

    #pragma unroll 1
    for (int jt = 0; jt < DD; jt += TJ) {
        float u2j = s_u2[jt + j];
        float m2j = fmaxf(u2j * smax, u2j * smin);
        float Zl = 0.0f;

        float* Ecol = E + (size_t)(g * 32) * ESTR + j;
        const float* sbase = s_s + g * 32;
        #pragma unroll
        for (int i4 = 0; i4 < 32; i4 += 4) {
            float4 s4 = *(const float4*)(sbase + i4);
            float e0 = ex2f(fmaf(s4.x, u2j, -m2j));
            float e1 = ex2f(fmaf(s4.y, u2j, -m2j));
            float e2 = ex2f(fmaf(s4.z, u2j, -m2j));
            float e3 = ex2f(fmaf(s4.w, u2j, -m2j));
            Zl += (e0 + e1) + (e2 + e3);
            Ecol[(i4 + 0) * ESTR] = e0;
            Ecol[(i4 + 1) * ESTR] = e1;
            Ecol[(i4 + 2) * ESTR] = e2;
            Ecol[(i4 + 3) * ESTR] = e3;
        }
        Zpart[g][j] = Zl;
        __syncthreads();

        if (tid < TJ) {
            float zt = 0.0f;
            #pragma unroll
            for (int w = 0; w < 16; w++) zt += Zpart[w][tid];
            coefT[tid] = s_v[jt + tid] / zt;
        }
        __syncthreads();

        const float* Erow = E + (size_t)tid * ESTR;
        #pragma unroll
        for (int jj = 0; jj < TJ; jj += 4) {
            float c0 = coefT[jj + 0], c1 = coefT[jj + 1];
            float c2 = coefT[jj + 2], c3 = coefT[jj + 3];
            acc = fmaf(c0, Erow[jj + 0], acc);
            acc = fmaf(c1, Erow[jj + 1], acc);
            acc = fmaf(c2, Erow[jj + 2], acc);
            acc = fmaf(c3, Erow[jj + 3], acc);
        }
        __syncthreads();
    }

    float y     = acc + vv;
    float mu_y  = blockReduceSum(y, red) * inv_d;
    float dy    = y - mu_y;
    float var_y = blockReduceSum(dy * dy, red) * inv_d;
    float yn    = dy * rsqrtf(var_y + EPSF) * norm_g[tid] + norm_b[tid];

    g_y[(size_t)row * DD + tid] = yn;
}

extern "C" void kernel_launch(void* const* d_in, const int* in_sizes, int n_in,
                              void* d_out, int out_size)
{
    (void)in_sizes; (void)n_in; (void)out_size;
    const float* r    = (const float*)d_in[0];
    const float* g    = (const float*)d_in[1];
    const float* b    = (const float*)d_in[2];
    const float* h_r  = (const float*)d_in[3];
    const float* h_g  = (const float*)d_in[4];
    const float* h_b  = (const float*)d_in[5];
    const float* k_r  = (const float*)d_in[6];
    const float* k_g  = (const float*)d_in[7];
    const float* k_b  = (const float*)d_in[8];
    const float* Wk   = (const float*)d_in[9];
    const float* bk   = (const float*)d_in[10];
    const float* Wq   = (const float*)d_in[11];
    const float* bq   = (const float*)d_in[12];
    const float* kn_g = (const float*)d_in[13];
    const float* kn_b = (const float*)d_in[14];
    const float* norm_g = (const float*)d_in[15];
    const float* norm_b = (const float*)d_in[16];
    const float* fc_w = (const float*)d_in[17];
    const float* fc_b = (const float*)d_in[18];
    float* out = (float*)d_out;

    Ptr3 X  = {{ r,   g,   b   }};
    Ptr3 H  = {{ h_r, h_g, h_b }};
    Ptr3 KQ = {{ k_r, k_g, k_b }};

    const size_t E_BYTES = (size_t)DD * (TJ + 1) * sizeof(float);

    static float* wt_dev = nullptr;
    static float* wk_dev = nullptr;
    static float* wq_dev = nullptr;
    static float* y_dev  = nullptr;
    if (wt_dev == nullptr) {
        void* p = nullptr;
        cudaGetSymbolAddress(&p, g_wt); wt_dev = (float*)p;
        cudaGetSymbolAddress(&p, g_wk); wk_dev = (float*)p;
        cudaGetSymbolAddress(&p, g_wq); wq_dev = (float*)p;
        cudaGetSymbolAddress(&p, g_y);  y_dev  = (float*)p;
        cudaFuncSetAttribute(k_main, cudaFuncAttributeMaxDynamicSharedMemorySize,
                             (int)E_BYTES);
        cudaFuncSetAttribute(k_gemm6<false>, cudaFuncAttributeMaxDynamicSharedMemorySize,
                             G6_SMEM);
        cudaFuncSetAttribute(k_gemm6<true>, cudaFuncAttributeMaxDynamicSharedMemorySize,
                             G6_SMEM);
    }

    // Stage 0: transpose weights -> g_wt (k-major)
    k_transpose<<<dim3(16, 16, 3), dim3(32, 8)>>>(Wk, Wq, fc_w);

    // Stage 1: w_k = h @ Wk.T + bk ; w_q = kidx @ Wq.T + bq
    {
        G6 a;
        a.src[0] = H;            a.src[1] = KQ;
        a.wt[0]  = wt_dev;       a.wt[1]  = wt_dev + DD * DD;
        a.bias[0] = bk;          a.bias[1] = bq;
        a.out[0] = wk_dev;       a.out[1] = wq_dev;
        k_gemm6<false><<<dim3(24, 8, 2), 128, G6_SMEM>>>(a);
    }

    // Stage 2: collapsed attention + residual + LN -> g_y
    k_main<<<dim3(BB, 3), 512, E_BYTES>>>(X, H, KQ, kn_g, kn_b, norm_g, norm_b);

    // Stage 3: out = y @ fc_w.T + fc_b + y
    {
        Ptr3 Y = {{ y_dev, y_dev + BB * DD, y_dev + 2 * BB * DD }};
        G6 a;
        a.src[0] = Y;            a.src[1] = Y;
        a.wt[0]  = wt_dev + 2 * DD * DD;  a.wt[1] = a.wt[0];
        a.bias[0] = fc_b;        a.bias[1] = fc_b;
        a.out[0] = out;          a.out[1] = out;
        k_gemm6<true><<<dim3(24, 8, 1), 128, G6_SMEM>>>(a);
    }
}